// round 10
// baseline (speedup 1.0000x reference)
#include <cuda_runtime.h>
#include <cstdint>

// Conv2D 15x15 valid cross-correlation, 4096x4096 fp32 -> 4082x4082 fp32.
// Banded-Toeplitz implicit GEMM via legacy tensor-core mma.sync
// (m16n8k8 tf32, sm_80 PTX -> compiles under compute_100).
//
// Per CTA: D[M=128 oy][N=16 ox] = sum_{ky=0..14} A_ky @ B_ky, where
//   A_ky[m][k] = X[gy0+m+ky][gx0+k]          (k = 0..31 input columns)
//   B_ky[k][n] = w[ky][k-n] if 0<=k-n<15     (banded Toeplitz)
// Band => n-tile 0 (n 0..7) needs k-chunks {0,1,2}; n-tile 1 needs {1,2,3}.
// 12 MMAs per ky per warp, 180 total; fp32 accumulate in registers.
//
// smem layouts engineered so every fragment load is ONE conflict-free
// LDS.64: columns permuted so (k, k+4) are adjacent; A pitch 40 floats makes
// half-warp bank index (4r+c) a perfect permutation.

#define H_IN  4096
#define W_IN  4096
#define KH    15
#define KW    15
#define OH    (H_IN - KH + 1)   // 4082
#define OW    (W_IN - KW + 1)   // 4082

#define TM    128               // oy per CTA
#define TN    16                // ox per CTA
#define KDIM  32
#define AROWS (TM + KH - 1)     // 142
#define APITCH 40               // floats
#define NT    128

__device__ __forceinline__ uint32_t tf32r(float f) {
    uint32_t r; asm("cvt.rna.tf32.f32 %0, %1;" : "=r"(r) : "f"(f)); return r;
}

__device__ __forceinline__ void mma_tf32(float (&acc)[4],
                                         float2 a02, float2 a13, float2 b) {
    asm volatile(
        "mma.sync.aligned.m16n8k8.row.col.f32.tf32.tf32.f32 "
        "{%0,%1,%2,%3}, {%4,%5,%6,%7}, {%8,%9}, {%0,%1,%2,%3};"
        : "+f"(acc[0]), "+f"(acc[1]), "+f"(acc[2]), "+f"(acc[3])
        : "r"(__float_as_uint(a02.x)),   // a0: (r,   k)
          "r"(__float_as_uint(a13.x)),   // a1: (r+8, k)
          "r"(__float_as_uint(a02.y)),   // a2: (r,   k+4)
          "r"(__float_as_uint(a13.y)),   // a3: (r+8, k+4)
          "r"(__float_as_uint(b.x)),     // b0: (k,   n)
          "r"(__float_as_uint(b.y)));    // b1: (k+4, n)
}

__global__ __launch_bounds__(NT)
void conv15_hmma_kernel(const float* __restrict__ X,
                        const float* __restrict__ Wt,
                        const float* __restrict__ bias,
                        float* __restrict__ out)
{
    // A: 142 rows x 32 cols (col-permuted), pitch 40 floats.
    __shared__ __align__(16) float sA[AROWS * APITCH];         // 22720 B
    // B: [ky][nt][jj] 8x8 blocks (k-permuted, stored [n][k']).
    __shared__ __align__(16) float sB[KH * 2 * 3 * 64];        // 23040 B

    const int tid  = threadIdx.x;
    const int warp = tid >> 5;
    const int lane = tid & 31;
    const int gx0  = blockIdx.x * TN;
    const int gy0  = blockIdx.y * TM;

    // ---- A fill: coalesced rows, tf32 round, column permute ----
    // perm within 8-col chunk: (0,4)->(0,1) (1,5)->(2,3) (2,6)->(4,5) (3,7)->(6,7)
    for (int i = tid; i < AROWS * KDIM; i += NT) {
        int r = i >> 5, c = i & 31;
        int gy = gy0 + r; if (gy > H_IN - 1) gy = H_IN - 1;
        int gx = gx0 + c; if (gx > W_IN - 1) gx = W_IN - 1;
        int cc = c & 7;
        int cp = (c & 24) | ((cc & 3) << 1) | (cc >> 2);
        sA[r * APITCH + cp] = __uint_as_float(tf32r(X[(size_t)gy * W_IN + gx]));
    }
    // ---- B fill: banded Toeplitz blocks (jj unrolled; no int divides) ----
    #pragma unroll
    for (int jj = 0; jj < 3; jj++) {
        for (int u = tid; u < KH * 2 * 64; u += NT) {
            int e  = u & 63;         // n_local*8 + k'
            int q  = u >> 6;         // ky*2 + nt
            int nt = q & 1, ky = q >> 1;
            int nl = e >> 3, kp = e & 7;
            int kl = (kp >> 1) | ((kp & 1) << 2);   // inverse permute
            int k  = (jj + nt) * 8 + kl;
            int kx = k - (nt * 8 + nl);
            float v = (kx >= 0 && kx < KW) ? Wt[ky * KW + kx] : 0.0f;
            sB[(q * 3 + jj) * 64 + e] = __uint_as_float(tf32r(v));
        }
    }
    __syncthreads();

    float acc[2][2][4];
    #pragma unroll
    for (int mt = 0; mt < 2; mt++)
        #pragma unroll
        for (int nt = 0; nt < 2; nt++)
            #pragma unroll
            for (int f = 0; f < 4; f++) acc[mt][nt][f] = 0.0f;

    const int rA = warp * 32 + (lane >> 2);   // fragment row (mt=0, a0)
    const int c2 = (lane & 3) * 2;            // permuted col of (k,k+4) pair
    const int bOff = (lane >> 2) * 8 + c2;

    #pragma unroll 1
    for (int ky = 0; ky < KH; ky++) {
        const float* ap0 = &sA[(rA + ky) * APITCH + c2];
        float2 A02[2][4], A13[2][4];
        #pragma unroll
        for (int mt = 0; mt < 2; mt++) {
            const float* ap = ap0 + mt * (16 * APITCH);
            #pragma unroll
            for (int j = 0; j < 4; j++) {
                A02[mt][j] = *(const float2*)(ap + 8 * j);
                A13[mt][j] = *(const float2*)(ap + 8 * APITCH + 8 * j);
            }
        }
        float2 Bf[2][3];
        #pragma unroll
        for (int nt = 0; nt < 2; nt++)
            #pragma unroll
            for (int jj = 0; jj < 3; jj++)
                Bf[nt][jj] = *(const float2*)&sB[((ky * 2 + nt) * 3 + jj) * 64 + bOff];

        #pragma unroll
        for (int mt = 0; mt < 2; mt++)
            #pragma unroll
            for (int nt = 0; nt < 2; nt++)
                #pragma unroll
                for (int jj = 0; jj < 3; jj++)
                    mma_tf32(acc[mt][nt], A02[mt][jj + nt], A13[mt][jj + nt],
                             Bf[nt][jj]);
    }

    // ---- epilogue: c0,c1 -> row r; c2,c3 -> row r+8; cols 2(lane&3)+{0,1} ----
    const float bv = bias[0];
    #pragma unroll
    for (int mt = 0; mt < 2; mt++) {
        #pragma unroll
        for (int half = 0; half < 2; half++) {
            int oy = gy0 + warp * 32 + 16 * mt + (lane >> 2) + 8 * half;
            if (oy < OH) {
                #pragma unroll
                for (int nt = 0; nt < 2; nt++) {
                    int ox = gx0 + 8 * nt + c2;
                    if (ox < OW) {      // ox,OW even -> pair fits
                        float2 v;
                        v.x = acc[mt][nt][2 * half]     + bv;
                        v.y = acc[mt][nt][2 * half + 1] + bv;
                        *(float2*)&out[(size_t)oy * OW + ox] = v;
                    }
                }
            }
        }
    }
}

extern "C" void kernel_launch(void* const* d_in, const int* in_sizes, int n_in,
                              void* d_out, int out_size)
{
    const float* X    = (const float*)d_in[0];  // [4096,4096]
    const float* Wt   = (const float*)d_in[1];  // [15,15]
    const float* bias = (const float*)d_in[2];  // [1]
    float* out        = (float*)d_out;          // [4082,4082]

    dim3 grid((OW + TN - 1) / TN,    // 256
              (OH + TM - 1) / TM);   // 32
    conv15_hmma_kernel<<<grid, NT>>>(X, Wt, bias, out);
}

// round 11
// speedup vs baseline: 1.3750x; 1.3750x over previous
#include <cuda_runtime.h>
#include <cstdint>

// Conv2D 15x15 valid cross-correlation, 4096x4096 fp32 -> 4082x4082 fp32.
// Banded-Toeplitz implicit GEMM, legacy mma.sync m16n8k8 tf32 (sm_80 PTX).
//
// Key fact: Toeplitz block (nt,jj) = w[ky][jj*8 + kl - nl] is nt-INDEPENDENT,
// so B needs only 3 8x8 blocks per ky (deduped), and 3 B fragments per ky
// feed every (mt,nt) MMA of the warp.
//
// Warp tile: 32(oy) x 32(ox); CTA: 4 warps stacked in M = 128 x 32.
// K = 48 input cols (6 chunks of 8). Per warp per ky:
//   24 A LDS.64 + 3 B LDS.64 -> 24 MMAs  (MMA(nt,jj) uses A chunk nt+jj).
// fp32 register accumulation; tf32 inputs (rel_err ~3e-4, gate is 1e-3).
//
// smem: A 142 rows x 48 cols (col-permuted (k,k+4) adjacent), pitch 56
// (28 float2 === 12 mod 16 -> half-warp bank index is a permutation for
// every row/chunk/ky offset). B: 15*3 8x8 blocks, [n][k'] layout.

#define H_IN  4096
#define W_IN  4096
#define KH    15
#define KW    15
#define OH    (H_IN - KH + 1)   // 4082
#define OW    (W_IN - KW + 1)   // 4082

#define TM    128               // oy per CTA
#define TN    32                // ox per CTA
#define KDIM  48                // input cols per tile
#define NCH   6                 // k-chunks
#define AROWS (TM + KH - 1)     // 142
#define APITCH 56               // floats
#define NT    128

__device__ __forceinline__ uint32_t tf32r(float f) {
    uint32_t r; asm("cvt.rna.tf32.f32 %0, %1;" : "=r"(r) : "f"(f)); return r;
}

__device__ __forceinline__ void mma_tf32(float (&acc)[4],
                                         float2 a02, float2 a13, float2 b) {
    asm volatile(
        "mma.sync.aligned.m16n8k8.row.col.f32.tf32.tf32.f32 "
        "{%0,%1,%2,%3}, {%4,%5,%6,%7}, {%8,%9}, {%0,%1,%2,%3};"
        : "+f"(acc[0]), "+f"(acc[1]), "+f"(acc[2]), "+f"(acc[3])
        : "r"(__float_as_uint(a02.x)),   // a0: (r,   k)
          "r"(__float_as_uint(a13.x)),   // a1: (r+8, k)
          "r"(__float_as_uint(a02.y)),   // a2: (r,   k+4)
          "r"(__float_as_uint(a13.y)),   // a3: (r+8, k+4)
          "r"(__float_as_uint(b.x)),     // b0: (k,   n)
          "r"(__float_as_uint(b.y)));    // b1: (k+4, n)
}

__global__ __launch_bounds__(NT)
void conv15_hmma2_kernel(const float* __restrict__ X,
                         const float* __restrict__ Wt,
                         const float* __restrict__ bias,
                         float* __restrict__ out)
{
    __shared__ __align__(16) float sA[AROWS * APITCH];   // 31808 B
    __shared__ __align__(16) float sB[KH * 3 * 64];      // 11520 B

    const int tid  = threadIdx.x;
    const int warp = tid >> 5;
    const int lane = tid & 31;
    const int gx0  = blockIdx.x * TN;
    const int gy0  = blockIdx.y * TM;

    // ---- A fill: 142 x 48, tf32 round, (k,k+4)-adjacent column permute ----
    for (int i = tid; i < AROWS * KDIM; i += NT) {
        int r = i / KDIM, c = i - r * KDIM;
        int gy = gy0 + r; if (gy > H_IN - 1) gy = H_IN - 1;
        int gx = gx0 + c; if (gx > W_IN - 1) gx = W_IN - 1;
        int cc = c & 7;
        int cp = (c & ~7) | ((cc & 3) << 1) | (cc >> 2);
        sA[r * APITCH + cp] = __uint_as_float(tf32r(X[(size_t)gy * W_IN + gx]));
    }
    // ---- B fill: 15 ky x 3 jj deduped Toeplitz blocks, [n][k'] 8x8 ----
    for (int i = tid; i < KH * 3 * 64; i += NT) {
        int e  = i & 63;          // nl*8 + k'
        int t  = i >> 6;          // ky*3 + jj
        int jj = t % 3, ky = t / 3;
        int nl = e >> 3, kp = e & 7;
        int kl = (kp >> 1) | ((kp & 1) << 2);    // inverse column permute
        int kx = jj * 8 + kl - nl;
        float v = (kx >= 0 && kx < KW) ? Wt[ky * KW + kx] : 0.0f;
        sB[i] = __uint_as_float(tf32r(v));
    }
    __syncthreads();

    float acc[2][4][4];
    #pragma unroll
    for (int mt = 0; mt < 2; mt++)
        #pragma unroll
        for (int nt = 0; nt < 4; nt++)
            #pragma unroll
            for (int f = 0; f < 4; f++) acc[mt][nt][f] = 0.0f;

    const int rA   = warp * 32 + (lane >> 2);   // fragment base row (mt=0)
    const int c2   = (lane & 3) * 2;            // permuted (k,k+4) pair col
    const int bOff = (lane >> 2) * 8 + c2;      // B block: [n][k']

    #pragma unroll 1
    for (int ky = 0; ky < KH; ky++) {
        float2 Bf[3];
        #pragma unroll
        for (int jj = 0; jj < 3; jj++)
            Bf[jj] = *(const float2*)&sB[(ky * 3 + jj) * 64 + bOff];

        #pragma unroll
        for (int mt = 0; mt < 2; mt++) {
            const float* ap = &sA[(rA + ky + mt * 16) * APITCH + c2];
            float2 A02[NCH], A13[NCH];
            #pragma unroll
            for (int ch = 0; ch < NCH; ch++) {
                A02[ch] = *(const float2*)(ap + 8 * ch);
                A13[ch] = *(const float2*)(ap + 8 * APITCH + 8 * ch);
            }
            #pragma unroll
            for (int jj = 0; jj < 3; jj++)
                #pragma unroll
                for (int nt = 0; nt < 4; nt++)   // nt-inner: 4 indep chains
                    mma_tf32(acc[mt][nt], A02[nt + jj], A13[nt + jj], Bf[jj]);
        }
    }

    // ---- epilogue: c0,c1 -> row r; c2,c3 -> row r+8; cols nt*8 + c2 ----
    const float bv = bias[0];
    #pragma unroll
    for (int mt = 0; mt < 2; mt++) {
        #pragma unroll
        for (int half = 0; half < 2; half++) {
            int oy = gy0 + warp * 32 + 16 * mt + (lane >> 2) + 8 * half;
            if (oy < OH) {
                #pragma unroll
                for (int nt = 0; nt < 4; nt++) {
                    int ox = gx0 + 8 * nt + c2;
                    if (ox < OW) {      // ox,OW even -> pair fits
                        float2 v;
                        v.x = acc[mt][nt][2 * half]     + bv;
                        v.y = acc[mt][nt][2 * half + 1] + bv;
                        *(float2*)&out[(size_t)oy * OW + ox] = v;
                    }
                }
            }
        }
    }
}

extern "C" void kernel_launch(void* const* d_in, const int* in_sizes, int n_in,
                              void* d_out, int out_size)
{
    const float* X    = (const float*)d_in[0];  // [4096,4096]
    const float* Wt   = (const float*)d_in[1];  // [15,15]
    const float* bias = (const float*)d_in[2];  // [1]
    float* out        = (float*)d_out;          // [4082,4082]

    dim3 grid((OW + TN - 1) / TN,    // 128
              (OH + TM - 1) / TM);   // 32
    conv15_hmma2_kernel<<<grid, NT>>>(X, Wt, bias, out);
}